// round 2
// baseline (speedup 1.0000x reference)
#include <cuda_runtime.h>
#include <stdint.h>

// ---------------------------------------------------------------------------
// KMaxPool: for each row of 4096 fp32, output the top-8 values in original
// index order. One warp per row, single pass over HBM, selection in registers.
//
// Total order for selection: value descending, index ascending for ties
// (matches jax.lax.top_k first-occurrence semantics). Encoded as a u64 key:
//   hi32 = order-preserving transform of the float bits
//   lo32 = ~idx   (so larger key == smaller index on value ties)
// ---------------------------------------------------------------------------

static __device__ __forceinline__ unsigned long long fkey(float v, uint32_t idx) {
    uint32_t b = __float_as_uint(v);
    uint32_t u = (b & 0x80000000u) ? ~b : (b | 0x80000000u);  // monotone in v
    return ((unsigned long long)u << 32) | (uint32_t)(~idx);
}

static __device__ __forceinline__ float kval(unsigned long long k) {
    uint32_t u = (uint32_t)(k >> 32);
    uint32_t b = (u & 0x80000000u) ? (u ^ 0x80000000u) : ~u;
    return __uint_as_float(b);
}

// Sentinel: -inf with worst tie-break index. Decodes back to -inf via kval.
#define SENTINEL_KEY 0x007FFFFF00000000ull

// keep larger key in `a` (descending order compare-exchange)
#define CSWAP_DESC(a, b)                                     \
    do {                                                     \
        if ((a) < (b)) {                                     \
            unsigned long long _t = (a); (a) = (b); (b) = _t;\
        }                                                    \
    } while (0)

__global__ void __launch_bounds__(256) kmax8_kernel(const float* __restrict__ x,
                                                    float* __restrict__ out,
                                                    int nrows) {
    const int gw   = (int)((blockIdx.x * blockDim.x + threadIdx.x) >> 5);
    const int lane = threadIdx.x & 31;
    if (gw >= nrows) return;

    const float4* row = reinterpret_cast<const float4*>(x) + (size_t)gw * 1024;

    unsigned long long t[8];
#pragma unroll
    for (int i = 0; i < 8; ++i) t[i] = SENTINEL_KEY;
    float vmin = __int_as_float(0xff800000);  // -inf

    // Insert one candidate into the sorted-descending 8-list.
    // Lane-local stream is in ascending idx order, so on value ties the
    // incumbent (earlier idx) correctly wins via the strict compare.
    auto consider = [&](float v, uint32_t idx) {
        if (v > vmin) {
            t[7] = fkey(v, idx);
#pragma unroll
            for (int j = 7; j > 0; --j) {
                if (t[j] > t[j - 1]) {
                    unsigned long long tmp = t[j]; t[j] = t[j - 1]; t[j - 1] = tmp;
                }
            }
            vmin = kval(t[7]);
        }
    };

    // 32 float4 per lane, batched 4 at a time for MLP.
#pragma unroll 1
    for (int it = 0; it < 8; ++it) {
        const int i0 = (it * 4 + 0) * 32 + lane;
        const int i1 = (it * 4 + 1) * 32 + lane;
        const int i2 = (it * 4 + 2) * 32 + lane;
        const int i3 = (it * 4 + 3) * 32 + lane;
        float4 v0 = row[i0];
        float4 v1 = row[i1];
        float4 v2 = row[i2];
        float4 v3 = row[i3];
        uint32_t b0 = (uint32_t)i0 * 4u;
        uint32_t b1 = (uint32_t)i1 * 4u;
        uint32_t b2 = (uint32_t)i2 * 4u;
        uint32_t b3 = (uint32_t)i3 * 4u;
        consider(v0.x, b0 + 0); consider(v0.y, b0 + 1);
        consider(v0.z, b0 + 2); consider(v0.w, b0 + 3);
        consider(v1.x, b1 + 0); consider(v1.y, b1 + 1);
        consider(v1.z, b1 + 2); consider(v1.w, b1 + 3);
        consider(v2.x, b2 + 0); consider(v2.y, b2 + 1);
        consider(v2.z, b2 + 2); consider(v2.w, b2 + 3);
        consider(v3.x, b3 + 0); consider(v3.y, b3 + 1);
        consider(v3.z, b3 + 2); consider(v3.w, b3 + 3);
    }

    // Warp butterfly merge: 5 rounds. Each round merges two sorted-desc lists
    // via the bitonic max-trick, then a 3-stage bitonic clean of 8.
#pragma unroll
    for (int m = 16; m >= 1; m >>= 1) {
        unsigned long long c[8];
#pragma unroll
        for (int i = 0; i < 8; ++i) {
            unsigned long long b = __shfl_xor_sync(0xffffffffu, t[7 - i], m);
            c[i] = (t[i] > b) ? t[i] : b;   // top-8 of union, bitonic sequence
        }
        CSWAP_DESC(c[0], c[4]); CSWAP_DESC(c[1], c[5]);
        CSWAP_DESC(c[2], c[6]); CSWAP_DESC(c[3], c[7]);
        CSWAP_DESC(c[0], c[2]); CSWAP_DESC(c[1], c[3]);
        CSWAP_DESC(c[4], c[6]); CSWAP_DESC(c[5], c[7]);
        CSWAP_DESC(c[0], c[1]); CSWAP_DESC(c[2], c[3]);
        CSWAP_DESC(c[4], c[5]); CSWAP_DESC(c[6], c[7]);
#pragma unroll
        for (int i = 0; i < 8; ++i) t[i] = c[i];
    }

    // Every lane now holds the identical global top-8 (value-desc).
    // Reorder by ascending original index == descending lo32 (~idx).
#pragma unroll
    for (int i = 0; i < 7; ++i) {
#pragma unroll
        for (int j = 0; j < 7 - i; ++j) {
            if ((uint32_t)t[j] < (uint32_t)t[j + 1]) {
                unsigned long long tmp = t[j]; t[j] = t[j + 1]; t[j + 1] = tmp;
            }
        }
    }

    if (lane == 0) {
        float* o = out + (size_t)gw * 8;
#pragma unroll
        for (int i = 0; i < 8; ++i) o[i] = kval(t[i]);
    }
}

extern "C" void kernel_launch(void* const* d_in, const int* in_sizes, int n_in,
                              void* d_out, int out_size) {
    const float* x = (const float*)d_in[0];
    float* out = (float*)d_out;
    // rows of length 4096 over the last axis; k fixed at 8 (reference setup)
    int nrows = in_sizes[0] / 4096;
    const int threads = 256;
    const int warps_per_block = threads / 32;
    int blocks = (nrows + warps_per_block - 1) / warps_per_block;
    kmax8_kernel<<<blocks, threads>>>(x, out, nrows);
}

// round 3
// speedup vs baseline: 1.0769x; 1.0769x over previous
#include <cuda_runtime.h>
#include <stdint.h>

// ---------------------------------------------------------------------------
// KMaxPool: per row of 4096 fp32, output top-8 values in original index order.
// One warp per row. ALU-lean single pass:
//   - 16-element chunks per lane, FMNMX-tree chunk max vs threshold (1 op/elem)
//   - warp-refreshed threshold T = warp_max(lane 8th value) after each chunk
//     (safe: v8(union) >= v8(subset); ties at T provably lose on index)
//   - rare qualifying chunks rescanned with exact 64-bit keyed insertion
//   - one exact 64-bit bitonic warp merge at the end
// Key: hi32 = order-preserving float bits, lo32 = ~idx (value desc, idx asc).
// ---------------------------------------------------------------------------

static __device__ __forceinline__ unsigned long long fkey(float v, uint32_t idx) {
    uint32_t b = __float_as_uint(v);
    uint32_t u = (b & 0x80000000u) ? ~b : (b | 0x80000000u);
    return ((unsigned long long)u << 32) | (uint32_t)(~idx);
}

static __device__ __forceinline__ float kval(unsigned long long k) {
    uint32_t u = (uint32_t)(k >> 32);
    uint32_t b = (u & 0x80000000u) ? (u ^ 0x80000000u) : ~u;
    return __uint_as_float(b);
}

// Sentinel: -inf with worst tie-break index. kval(SENTINEL_KEY) == -inf.
#define SENTINEL_KEY 0x007FFFFF00000000ull

#define CSWAP_DESC(a, b)                                     \
    do {                                                     \
        if ((a) < (b)) {                                     \
            unsigned long long _t = (a); (a) = (b); (b) = _t;\
        }                                                    \
    } while (0)

__global__ void __launch_bounds__(256) kmax8_kernel(const float* __restrict__ x,
                                                    float* __restrict__ out,
                                                    int nrows) {
    const int gw   = (int)((blockIdx.x * blockDim.x + threadIdx.x) >> 5);
    const int lane = threadIdx.x & 31;
    if (gw >= nrows) return;

    const float4* row = reinterpret_cast<const float4*>(x) + (size_t)gw * 1024;

    unsigned long long t[8];
#pragma unroll
    for (int i = 0; i < 8; ++i) t[i] = SENTINEL_KEY;
    float vmin = __int_as_float(0xff800000);  // reject threshold (-inf)

    // Exact 64-bit keyed insert (only on qualifying elements; rare).
    auto consider = [&](float v, uint32_t idx) {
        if (v > vmin) {
            t[7] = fkey(v, idx);
#pragma unroll
            for (int j = 7; j > 0; --j) {
                if (t[j] > t[j - 1]) {
                    unsigned long long tmp = t[j]; t[j] = t[j - 1]; t[j - 1] = tmp;
                }
            }
            // never let vmin drop below the warp threshold already absorbed
            vmin = fmaxf(vmin, kval(t[7]));
        }
    };

    // 8 iterations x 16 elements per lane = 128 elements/lane = 4096/row.
#pragma unroll 1
    for (int it = 0; it < 8; ++it) {
        const int p0 = it * 128 + 0 * 32 + lane;
        const int p1 = it * 128 + 1 * 32 + lane;
        const int p2 = it * 128 + 2 * 32 + lane;
        const int p3 = it * 128 + 3 * 32 + lane;
        float4 v0 = row[p0];
        float4 v1 = row[p1];
        float4 v2 = row[p2];
        float4 v3 = row[p3];

        // chunk max: 15 FMNMX, deep ILP
        float m0 = fmaxf(fmaxf(v0.x, v0.y), fmaxf(v0.z, v0.w));
        float m1 = fmaxf(fmaxf(v1.x, v1.y), fmaxf(v1.z, v1.w));
        float m2 = fmaxf(fmaxf(v2.x, v2.y), fmaxf(v2.z, v2.w));
        float m3 = fmaxf(fmaxf(v3.x, v3.y), fmaxf(v3.z, v3.w));
        float cmax = fmaxf(fmaxf(m0, m1), fmaxf(m2, m3));

        if (cmax > vmin) {
            // rescan in ascending index order (q asc, component asc)
            uint32_t b0 = (uint32_t)p0 * 4u;
            uint32_t b1 = (uint32_t)p1 * 4u;
            uint32_t b2 = (uint32_t)p2 * 4u;
            uint32_t b3 = (uint32_t)p3 * 4u;
            consider(v0.x, b0 + 0); consider(v0.y, b0 + 1);
            consider(v0.z, b0 + 2); consider(v0.w, b0 + 3);
            consider(v1.x, b1 + 0); consider(v1.y, b1 + 1);
            consider(v1.z, b1 + 2); consider(v1.w, b1 + 3);
            consider(v2.x, b2 + 0); consider(v2.y, b2 + 1);
            consider(v2.z, b2 + 2); consider(v2.w, b2 + 3);
            consider(v3.x, b3 + 0); consider(v3.y, b3 + 1);
            consider(v3.z, b3 + 2); consider(v3.w, b3 + 3);
        }

        // Warp-wide threshold refresh: T = max over lanes of lane 8th value.
        // v8(union of lane lists) >= v8(each lane list) >= each lane's t[7],
        // and v8(union) >= max_lane(t[7]) = T. Any future v <= T cannot enter
        // the final top-8 (ties at T lose on index to already-held elements).
        float my8 = kval(t[7]);
#pragma unroll
        for (int m = 16; m >= 1; m >>= 1)
            my8 = fmaxf(my8, __shfl_xor_sync(0xffffffffu, my8, m));
        vmin = fmaxf(vmin, my8);
    }

    // Exact warp butterfly merge: 5 rounds of (reverse-max merge + bitonic
    // clean of 8). Lane lists are disjoint multisets -> union is the row.
#pragma unroll
    for (int m = 16; m >= 1; m >>= 1) {
        unsigned long long c[8];
#pragma unroll
        for (int i = 0; i < 8; ++i) {
            unsigned long long b = __shfl_xor_sync(0xffffffffu, t[7 - i], m);
            c[i] = (t[i] > b) ? t[i] : b;
        }
        CSWAP_DESC(c[0], c[4]); CSWAP_DESC(c[1], c[5]);
        CSWAP_DESC(c[2], c[6]); CSWAP_DESC(c[3], c[7]);
        CSWAP_DESC(c[0], c[2]); CSWAP_DESC(c[1], c[3]);
        CSWAP_DESC(c[4], c[6]); CSWAP_DESC(c[5], c[7]);
        CSWAP_DESC(c[0], c[1]); CSWAP_DESC(c[2], c[3]);
        CSWAP_DESC(c[4], c[5]); CSWAP_DESC(c[6], c[7]);
#pragma unroll
        for (int i = 0; i < 8; ++i) t[i] = c[i];
    }

    // Reorder global top-8 by ascending original index (= descending ~idx).
#pragma unroll
    for (int i = 0; i < 7; ++i) {
#pragma unroll
        for (int j = 0; j < 7 - i; ++j) {
            if ((uint32_t)t[j] < (uint32_t)t[j + 1]) {
                unsigned long long tmp = t[j]; t[j] = t[j + 1]; t[j + 1] = tmp;
            }
        }
    }

    if (lane == 0) {
        float* o = out + (size_t)gw * 8;
#pragma unroll
        for (int i = 0; i < 8; ++i) o[i] = kval(t[i]);
    }
}

extern "C" void kernel_launch(void* const* d_in, const int* in_sizes, int n_in,
                              void* d_out, int out_size) {
    const float* x = (const float*)d_in[0];
    float* out = (float*)d_out;
    int nrows = in_sizes[0] / 4096;
    const int threads = 256;
    const int warps_per_block = threads / 32;
    int blocks = (nrows + warps_per_block - 1) / warps_per_block;
    kmax8_kernel<<<blocks, threads>>>(x, out, nrows);
}